// round 1
// baseline (speedup 1.0000x reference)
#include <cuda_runtime.h>

#define T_STEPS 2048
#define BATCH   256
#define HID     64
#define GATES   256   // 4*HID
#define EMBED   128

typedef unsigned long long ull;

// Inter-layer hidden-state buffers (scratch via __device__ globals — allocation-free).
__device__ float g_buf0[(size_t)T_STEPS * BATCH * HID];   // layer0 output [t][b][j]
__device__ float g_buf1[(size_t)T_STEPS * BATCH * HID];   // layer1 output [t][b][j]
__device__ float g_last[BATCH * HID];                     // layer2 last hidden [b][j]

// ---- packed fp32x2 FMA (Blackwell) ----
__device__ __forceinline__ ull ffma2(ull a, ull b, ull c) {
    ull d;
    asm("fma.rn.f32x2 %0, %1, %2, %3;" : "=l"(d) : "l"(a), "l"(b), "l"(c));
    return d;
}
__device__ __forceinline__ float sumhalves(ull v) {
    float lo, hi;
    asm("mov.b64 {%0, %1}, %2;" : "=f"(lo), "=f"(hi) : "l"(v));
    return lo + hi;
}
__device__ __forceinline__ float sigm(float x) {
    return __fdividef(1.f, 1.f + __expf(-x));
}
__device__ __forceinline__ float tanhx(float x) {
    float e = __expf(2.f * x);
    return 1.f - __fdividef(2.f, e + 1.f);
}

// ============================================================================
// Layer 0: input dim = 1.  gates = x_t * Wih[:,0] + h @ Whh^T + bias
// 128 blocks x 256 threads; block handles batch rows {2*bid, 2*bid+1}.
// Thread g owns gate g for both rows; Whh row lives in registers (f32x2 pairs).
// ============================================================================
__global__ void __launch_bounds__(256, 1) lstm_l0(
    const float* __restrict__ x,
    const float* __restrict__ Wih, const float* __restrict__ Whh,
    const float* __restrict__ bih, const float* __restrict__ bhh)
{
    __shared__ __align__(16) float xs[2][T_STEPS];   // 16 KB: both x rows, loaded once
    __shared__ __align__(16) float hsm[2][HID];
    __shared__ float gsm[2][GATES];

    const int tid = threadIdx.x;
    const int b0  = blockIdx.x * 2;

    // stage x rows into smem (coalesced)
    for (int i = tid; i < 2 * T_STEPS; i += 256) {
        int r = i >> 11, t = i & (T_STEPS - 1);
        xs[r][t] = x[(size_t)(b0 + r) * T_STEPS + t];
    }

    const int g = tid;
    const float wih  = Wih[g];
    const float bias = bih[g] + bhh[g];

    ull w[32];
    const ull* wr = (const ull*)(Whh + g * HID);
#pragma unroll
    for (int q = 0; q < 32; q++) w[q] = wr[q];

    if (tid < 128) hsm[tid >> 6][tid & 63] = 0.f;
    float c_state = 0.f;
    const int r_ep = tid >> 6, j_ep = tid & 63;
    __syncthreads();

    for (int t = 0; t < T_STEPS; t++) {
        ull a0 = 0ull, a0b = 0ull, a1 = 0ull, a1b = 0ull;
        const double2* H0 = (const double2*)hsm[0];
        const double2* H1 = (const double2*)hsm[1];
#pragma unroll
        for (int q = 0; q < 16; q++) {
            double2 ha = H0[q];
            double2 hb = H1[q];
            a0  = ffma2(w[2*q],   __double_as_longlong(ha.x), a0);
            a0b = ffma2(w[2*q+1], __double_as_longlong(ha.y), a0b);
            a1  = ffma2(w[2*q],   __double_as_longlong(hb.x), a1);
            a1b = ffma2(w[2*q+1], __double_as_longlong(hb.y), a1b);
        }
        float v0 = sumhalves(a0) + sumhalves(a0b) + fmaf(wih, xs[0][t], bias);
        float v1 = sumhalves(a1) + sumhalves(a1b) + fmaf(wih, xs[1][t], bias);
        const int typ = g >> 6;                 // 0:i 1:f 2:g 3:o  (uniform per warp)
        if (typ == 2) { v0 = tanhx(v0); v1 = tanhx(v1); }
        else          { v0 = sigm(v0);  v1 = sigm(v1);  }
        gsm[0][g] = v0;
        gsm[1][g] = v1;
        __syncthreads();
        if (tid < 128) {
            float iv = gsm[r_ep][j_ep];
            float fv = gsm[r_ep][64 + j_ep];
            float gv = gsm[r_ep][128 + j_ep];
            float ov = gsm[r_ep][192 + j_ep];
            c_state = fv * c_state + iv * gv;
            float h = ov * tanhx(c_state);
            hsm[r_ep][j_ep] = h;
            g_buf0[((size_t)t * BATCH + b0) * HID + tid] = h;   // contiguous 128 floats
        }
        __syncthreads();
    }
}

// ============================================================================
// Layers 1 & 2: input dim = 64.  K = 128 ([h_prev_t || h_own]).
// MODE 1: in=g_buf0, out=g_buf1 (full sequence).  MODE 2: in=g_buf1, out=g_last.
// Input for step t+1 prefetched into registers while step t's dot runs.
// ============================================================================
template<int MODE>
__global__ void __launch_bounds__(256, 1) lstm_l12(
    const float* __restrict__ Wih, const float* __restrict__ Whh,
    const float* __restrict__ bih, const float* __restrict__ bhh)
{
    const float* in = (MODE == 1) ? g_buf0 : g_buf1;

    __shared__ __align__(16) float hcat[2][2 * HID];   // [0..63]=h_prev_t, [64..127]=h_own
    __shared__ float gsm[2][GATES];

    const int tid = threadIdx.x;
    const int b0  = blockIdx.x * 2;
    const int g   = tid;
    const float bias = bih[g] + bhh[g];

    ull w[64];
    const ull* wi = (const ull*)(Wih + g * HID);
    const ull* wh = (const ull*)(Whh + g * HID);
#pragma unroll
    for (int q = 0; q < 32; q++) { w[q] = wi[q]; w[32 + q] = wh[q]; }

    if (tid < 128) hcat[tid >> 6][64 + (tid & 63)] = 0.f;
    float c_state = 0.f;
    const int r_ep = tid >> 6, j_ep = tid & 63;

    float pf = 0.f;
    if (tid < 128) pf = in[(size_t)b0 * HID + tid];   // t=0 input (rows b0,b0+1 contiguous)

    for (int t = 0; t < T_STEPS; t++) {
        if (tid < 128) hcat[r_ep][j_ep] = pf;
        __syncthreads();   // input + previous h now visible
        if (tid < 128 && t + 1 < T_STEPS)
            pf = in[((size_t)(t + 1) * BATCH + b0) * HID + tid];   // hidden under the dot

        ull a0 = 0ull, a0b = 0ull, a1 = 0ull, a1b = 0ull;
        const double2* H0 = (const double2*)hcat[0];
        const double2* H1 = (const double2*)hcat[1];
#pragma unroll
        for (int q = 0; q < 32; q++) {
            double2 ha = H0[q];
            double2 hb = H1[q];
            a0  = ffma2(w[2*q],   __double_as_longlong(ha.x), a0);
            a0b = ffma2(w[2*q+1], __double_as_longlong(ha.y), a0b);
            a1  = ffma2(w[2*q],   __double_as_longlong(hb.x), a1);
            a1b = ffma2(w[2*q+1], __double_as_longlong(hb.y), a1b);
        }
        float v0 = sumhalves(a0) + sumhalves(a0b) + bias;
        float v1 = sumhalves(a1) + sumhalves(a1b) + bias;
        const int typ = g >> 6;
        if (typ == 2) { v0 = tanhx(v0); v1 = tanhx(v1); }
        else          { v0 = sigm(v0);  v1 = sigm(v1);  }
        gsm[0][g] = v0;
        gsm[1][g] = v1;
        __syncthreads();
        if (tid < 128) {
            float iv = gsm[r_ep][j_ep];
            float fv = gsm[r_ep][64 + j_ep];
            float gv = gsm[r_ep][128 + j_ep];
            float ov = gsm[r_ep][192 + j_ep];
            c_state = fv * c_state + iv * gv;
            float h = ov * tanhx(c_state);
            hcat[r_ep][64 + j_ep] = h;
            if (MODE == 1) {
                g_buf1[((size_t)t * BATCH + b0) * HID + tid] = h;
            } else {
                if (t == T_STEPS - 1) g_last[b0 * HID + tid] = h;
            }
        }
        __syncthreads();   // protects gsm/hcat against next iteration's writes
    }
}

// ============================================================================
// Final FC:  out[b][e] = g_last[b] . fcW[e] + fcb[e]   (256 x 128 outputs)
// ============================================================================
__global__ void __launch_bounds__(256) fc_kernel(
    const float* __restrict__ W, const float* __restrict__ bvec,
    float* __restrict__ out)
{
    const int idx = blockIdx.x * 256 + threadIdx.x;   // 32768
    const int b = idx >> 7, e = idx & 127;
    const float4* w4 = (const float4*)(W + e * HID);
    const float4* h4 = (const float4*)(g_last + b * HID);
    float acc = 0.f;
#pragma unroll
    for (int q = 0; q < 16; q++) {
        float4 a = w4[q], h = h4[q];
        acc = fmaf(a.x, h.x, acc);
        acc = fmaf(a.y, h.y, acc);
        acc = fmaf(a.z, h.z, acc);
        acc = fmaf(a.w, h.w, acc);
    }
    out[idx] = acc + bvec[e];
}

// ============================================================================
extern "C" void kernel_launch(void* const* d_in, const int* in_sizes, int n_in,
                              void* d_out, int out_size)
{
    const float* x    = (const float*)d_in[0];
    const float* Wih0 = (const float*)d_in[1];
    const float* Whh0 = (const float*)d_in[2];
    const float* bih0 = (const float*)d_in[3];
    const float* bhh0 = (const float*)d_in[4];
    const float* Wih1 = (const float*)d_in[5];
    const float* Whh1 = (const float*)d_in[6];
    const float* bih1 = (const float*)d_in[7];
    const float* bhh1 = (const float*)d_in[8];
    const float* Wih2 = (const float*)d_in[9];
    const float* Whh2 = (const float*)d_in[10];
    const float* bih2 = (const float*)d_in[11];
    const float* bhh2 = (const float*)d_in[12];
    const float* fcW  = (const float*)d_in[13];
    const float* fcb  = (const float*)d_in[14];

    lstm_l0 <<<BATCH / 2, 256>>>(x, Wih0, Whh0, bih0, bhh0);
    lstm_l12<1><<<BATCH / 2, 256>>>(Wih1, Whh1, bih1, bhh1);
    lstm_l12<2><<<BATCH / 2, 256>>>(Wih2, Whh2, bih2, bhh2);
    fc_kernel<<<(BATCH * EMBED) / 256, 256>>>(fcW, fcb, (float*)d_out);
}

// round 3
// speedup vs baseline: 1.0006x; 1.0006x over previous
#include <cuda_runtime.h>

#define T_STEPS 2048
#define BATCH   256
#define HID     64
#define EMBED   128

typedef unsigned long long ull;

// Inter-layer hidden-state buffers (scratch via __device__ globals — allocation-free).
__device__ float g_buf0[(size_t)T_STEPS * BATCH * HID];   // layer0 output [t][b][j]
__device__ float g_buf1[(size_t)T_STEPS * BATCH * HID];   // layer1 output [t][b][j]
__device__ float g_last[BATCH * HID];                     // layer2 last hidden [b][j]

// ---- packed fp32x2 FMA (Blackwell) ----
__device__ __forceinline__ ull ffma2(ull a, ull b, ull c) {
    ull d;
    asm("fma.rn.f32x2 %0, %1, %2, %3;" : "=l"(d) : "l"(a), "l"(b), "l"(c));
    return d;
}
__device__ __forceinline__ float sumhalves(ull v) {
    float lo, hi;
    asm("mov.b64 {%0, %1}, %2;" : "=f"(lo), "=f"(hi) : "l"(v));
    return lo + hi;
}
// HW tanh (MUFU.TANH) — single 16-cyc MUFU op, few-ulp accuracy.
__device__ __forceinline__ float fast_tanh(float x) {
    float y;
    asm("tanh.approx.f32 %0, %1;" : "=f"(y) : "f"(x));
    return y;
}
__device__ __forceinline__ float fast_sigm(float x) {
    return fmaf(fast_tanh(0.5f * x), 0.5f, 0.5f);
}

// Thread->gate map (all LSTM kernels):
//   warp w (0..7), lane l (0..31):  j = w*8 + (l>>2)  (hidden unit),  type = l&3
//   type: 0:i 1:f 2:g 3:o  -> weight row gr = type*64 + j  (PyTorch gate order)
// After per-type nonlinearity, 3 butterfly shuffles deliver (i,f,g,o) to the
// type==0 lane of each quad, which owns the c/h update for unit j.
// (Non-type0 lanes compute with permuted-but-bounded garbage; their results are
//  never stored. Sigmoid/tanh outputs are bounded, so no overflow.)

// ============================================================================
// Layer 0: input dim = 1.  2 batch rows per block, 128 blocks x 256 threads.
// ============================================================================
__global__ void __launch_bounds__(256, 1) lstm_l0(
    const float* __restrict__ x,
    const float* __restrict__ Wih, const float* __restrict__ Whh,
    const float* __restrict__ bih, const float* __restrict__ bhh)
{
    __shared__ __align__(16) float xs[2][T_STEPS];     // 16 KB: both x rows
    __shared__ __align__(16) float hs[2][2][HID];      // [parity][row][j]

    const int tid = threadIdx.x;
    const int b0  = blockIdx.x * 2;

    for (int i = tid; i < 2 * T_STEPS; i += 256) {
        int r = i >> 11, t = i & (T_STEPS - 1);
        xs[r][t] = x[(size_t)(b0 + r) * T_STEPS + t];
    }

    const int w = tid >> 5, l = tid & 31;
    const int j = (w << 3) | (l >> 2);
    const int type = l & 3;
    const int gr = type * HID + j;

    const float wih  = Wih[gr];
    const float bias = bih[gr] + bhh[gr];

    ull wreg[32];
    const ull* wr = (const ull*)(Whh + gr * HID);
#pragma unroll
    for (int q = 0; q < 32; q++) wreg[q] = wr[q];

    if (tid < 128) hs[0][tid >> 6][tid & 63] = 0.f;
    float c0 = 0.f, c1 = 0.f;
    __syncthreads();

    for (int t = 0; t < T_STEPS; t++) {
        const int cur = t & 1, nxt = cur ^ 1;
        ull a0 = 0ull, a0b = 0ull, a1 = 0ull, a1b = 0ull;
        const double2* H0 = (const double2*)hs[cur][0];
        const double2* H1 = (const double2*)hs[cur][1];
#pragma unroll
        for (int q = 0; q < 16; q++) {
            double2 ha = H0[q];
            double2 hb = H1[q];
            a0  = ffma2(wreg[2*q],   __double_as_longlong(ha.x), a0);
            a0b = ffma2(wreg[2*q+1], __double_as_longlong(ha.y), a0b);
            a1  = ffma2(wreg[2*q],   __double_as_longlong(hb.x), a1);
            a1b = ffma2(wreg[2*q+1], __double_as_longlong(hb.y), a1b);
        }
        float v0 = sumhalves(a0) + sumhalves(a0b) + fmaf(wih, xs[0][t], bias);
        float v1 = sumhalves(a1) + sumhalves(a1b) + fmaf(wih, xs[1][t], bias);
        if (type == 2) { v0 = fast_tanh(v0); v1 = fast_tanh(v1); }
        else           { v0 = fast_sigm(v0); v1 = fast_sigm(v1); }

        float f0 = __shfl_xor_sync(0xffffffffu, v0, 1);
        float g0 = __shfl_xor_sync(0xffffffffu, v0, 2);
        float o0 = __shfl_xor_sync(0xffffffffu, f0, 2);
        float f1 = __shfl_xor_sync(0xffffffffu, v1, 1);
        float g1 = __shfl_xor_sync(0xffffffffu, v1, 2);
        float o1 = __shfl_xor_sync(0xffffffffu, f1, 2);

        c0 = f0 * c0 + v0 * g0;
        c1 = f1 * c1 + v1 * g1;
        float h0 = o0 * fast_tanh(c0);
        float h1 = o1 * fast_tanh(c1);

        if (type == 0) {
            hs[nxt][0][j] = h0;
            hs[nxt][1][j] = h1;
            g_buf0[((size_t)t * BATCH + b0) * HID + j]       = h0;
            g_buf0[((size_t)t * BATCH + b0 + 1) * HID + j]   = h1;
        }
        __syncthreads();
    }
}

// ============================================================================
// Layers 1 & 2: input dim = 64; K = 128 ([h_prev_layer || h_own]).
// Double-buffered smem -> single barrier per step.
// MODE 1: in=g_buf0, out=g_buf1.  MODE 2: in=g_buf1, out=g_last (last h only).
// ============================================================================
template<int MODE>
__global__ void __launch_bounds__(256, 1) lstm_l12(
    const float* __restrict__ Wih, const float* __restrict__ Whh,
    const float* __restrict__ bih, const float* __restrict__ bhh)
{
    const float* in = (MODE == 1) ? g_buf0 : g_buf1;

    __shared__ __align__(16) float hc[2][2][2 * HID];  // [parity][row][0..63 in | 64..127 h]

    const int tid = threadIdx.x;
    const int b0  = blockIdx.x * 2;

    const int w = tid >> 5, l = tid & 31;
    const int j = (w << 3) | (l >> 2);
    const int type = l & 3;
    const int gr = type * HID + j;
    const float bias = bih[gr] + bhh[gr];

    ull wreg[64];
    const ull* wi = (const ull*)(Wih + gr * HID);
    const ull* wh = (const ull*)(Whh + gr * HID);
#pragma unroll
    for (int q = 0; q < 32; q++) { wreg[q] = wi[q]; wreg[32 + q] = wh[q]; }

    const int r_in = tid >> 6, j_in = tid & 63;
    if (tid < 128) {
        hc[0][r_in][64 + j_in] = 0.f;
        hc[0][r_in][j_in]      = in[(size_t)b0 * HID + tid];        // t = 0 input
    }
    float pf = 0.f;
    if (tid < 128)
        pf = in[((size_t)1 * BATCH + b0) * HID + tid];              // t = 1 input

    float c0 = 0.f, c1 = 0.f;
    __syncthreads();

    for (int t = 0; t < T_STEPS; t++) {
        const int cur = t & 1, nxt = cur ^ 1;
        ull a0 = 0ull, a0b = 0ull, a1 = 0ull, a1b = 0ull;
        const double2* H0 = (const double2*)hc[cur][0];
        const double2* H1 = (const double2*)hc[cur][1];
#pragma unroll
        for (int q = 0; q < 32; q++) {
            double2 ha = H0[q];
            double2 hb = H1[q];
            a0  = ffma2(wreg[2*q],   __double_as_longlong(ha.x), a0);
            a0b = ffma2(wreg[2*q+1], __double_as_longlong(ha.y), a0b);
            a1  = ffma2(wreg[2*q],   __double_as_longlong(hb.x), a1);
            a1b = ffma2(wreg[2*q+1], __double_as_longlong(hb.y), a1b);
        }
        float v0 = sumhalves(a0) + sumhalves(a0b) + bias;
        float v1 = sumhalves(a1) + sumhalves(a1b) + bias;
        if (type == 2) { v0 = fast_tanh(v0); v1 = fast_tanh(v1); }
        else           { v0 = fast_sigm(v0); v1 = fast_sigm(v1); }

        float f0 = __shfl_xor_sync(0xffffffffu, v0, 1);
        float g0 = __shfl_xor_sync(0xffffffffu, v0, 2);
        float o0 = __shfl_xor_sync(0xffffffffu, f0, 2);
        float f1 = __shfl_xor_sync(0xffffffffu, v1, 1);
        float g1 = __shfl_xor_sync(0xffffffffu, v1, 2);
        float o1 = __shfl_xor_sync(0xffffffffu, f1, 2);

        c0 = f0 * c0 + v0 * g0;
        c1 = f1 * c1 + v1 * g1;
        float h0 = o0 * fast_tanh(c0);
        float h1 = o1 * fast_tanh(c1);

        if (type == 0) {
            hc[nxt][0][64 + j] = h0;
            hc[nxt][1][64 + j] = h1;
            if (MODE == 1) {
                g_buf1[((size_t)t * BATCH + b0) * HID + j]     = h0;
                g_buf1[((size_t)t * BATCH + b0 + 1) * HID + j] = h1;
            } else if (t == T_STEPS - 1) {
                g_last[b0 * HID + j]       = h0;
                g_last[(b0 + 1) * HID + j] = h1;
            }
        }
        if (tid < 128) {
            hc[nxt][r_in][j_in] = pf;                               // input for t+1
            if (t + 2 < T_STEPS)
                pf = in[((size_t)(t + 2) * BATCH + b0) * HID + tid];
        }
        __syncthreads();
    }
}

// ============================================================================
// Final FC:  out[b][e] = g_last[b] . fcW[e] + fcb[e]
// ============================================================================
__global__ void __launch_bounds__(256) fc_kernel(
    const float* __restrict__ W, const float* __restrict__ bvec,
    float* __restrict__ out)
{
    const int idx = blockIdx.x * 256 + threadIdx.x;
    const int b = idx >> 7, e = idx & 127;
    const float4* w4 = (const float4*)(W + e * HID);
    const float4* h4 = (const float4*)(g_last + b * HID);
    float acc = 0.f;
#pragma unroll
    for (int q = 0; q < 16; q++) {
        float4 a = w4[q], h = h4[q];
        acc = fmaf(a.x, h.x, acc);
        acc = fmaf(a.y, h.y, acc);
        acc = fmaf(a.z, h.z, acc);
        acc = fmaf(a.w, h.w, acc);
    }
    out[idx] = acc + bvec[e];
}

// ============================================================================
extern "C" void kernel_launch(void* const* d_in, const int* in_sizes, int n_in,
                              void* d_out, int out_size)
{
    const float* x    = (const float*)d_in[0];
    const float* Wih0 = (const float*)d_in[1];
    const float* Whh0 = (const float*)d_in[2];
    const float* bih0 = (const float*)d_in[3];
    const float* bhh0 = (const float*)d_in[4];
    const float* Wih1 = (const float*)d_in[5];
    const float* Whh1 = (const float*)d_in[6];
    const float* bih1 = (const float*)d_in[7];
    const float* bhh1 = (const float*)d_in[8];
    const float* Wih2 = (const float*)d_in[9];
    const float* Whh2 = (const float*)d_in[10];
    const float* bih2 = (const float*)d_in[11];
    const float* bhh2 = (const float*)d_in[12];
    const float* fcW  = (const float*)d_in[13];
    const float* fcb  = (const float*)d_in[14];

    lstm_l0 <<<BATCH / 2, 256>>>(x, Wih0, Whh0, bih0, bhh0);
    lstm_l12<1><<<BATCH / 2, 256>>>(Wih1, Whh1, bih1, bhh1);
    lstm_l12<2><<<BATCH / 2, 256>>>(Wih2, Whh2, bih2, bhh2);
    fc_kernel<<<(BATCH * EMBED) / 256, 256>>>(fcW, fcb, (float*)d_out);
}